// round 6
// baseline (speedup 1.0000x reference)
#include <cuda_runtime.h>

typedef unsigned long long ull;

#define NTHREADS 512
#define RAYS 8
#define NBLOCKS 4096          // 32768 / 8
#define B_TOTAL 32768

#define NW 68                 // padded column stride (floats) for transposed weights

// dynamic shared layout (in floats): four transposed 64x64 weight buffers
#define OFF_W0   0                         // 64*68 = 4352 each
#define OFF_W1   4352
#define OFF_W2   8704
#define OFF_W3   13056
#define OFF_OUT  17408                     // per-ray out state 8x(8x64)  (4096)
#define OFF_A    (OFF_OUT + 4096)          // per-ray attn accum          (4096)
#define OFF_QKV  (OFF_A + 4096)            // per-ray Q,K,V 8x3x(8x64)    (12288)
#define OFF_P    (OFF_QKV + 12288)         // per-ray probs/query 8x64    (512)
#define SMEM_FLOATS (OFF_P + 512)          // 38400 floats = 153.6 KB
#define SMEM_BYTES  (SMEM_FLOATS * 4)

struct Params {
  const float *query, *latent, *W1, *b1;
  const float *Wq, *bq, *Wk, *bk, *Wv, *bv, *Wo, *bo;
  const float *fW1, *fb1, *fW2, *fb2, *g1, *be1, *g2, *be2;
  const float *cWq, *cbq, *cWk, *cbk, *cWv, *cbv, *cWo, *cbo;
  const float *Wc, *bc, *Ws, *bs;
  float *o_color, *o_sigma, *o_out, *o_attn;
};

__device__ __forceinline__ ull ffma2(ull a, ull b, ull c) {
  ull d;
  asm("fma.rn.f32x2 %0, %1, %2, %3;" : "=l"(d) : "l"(a), "l"(b), "l"(c));
  return d;
}
__device__ __forceinline__ ull pack2(float lo, float hi) {
  ull d;
  asm("mov.b64 %0, {%1, %2};" : "=l"(d) : "f"(lo), "f"(hi));
  return d;
}
__device__ __forceinline__ float2 unpack2(ull v) {
  float lo, hi;
  asm("mov.b64 {%0, %1}, %2;" : "=f"(lo), "=f"(hi) : "l"(v));
  return make_float2(lo, hi);
}

// Stage a 64x64 weight block TRANSPOSED into dst[j*NW + d].
// 512 threads: 2 iters of 4 coalesced LDG.32 + 1 conflict-free STS.128.
__device__ __forceinline__ void stage_t(const float* __restrict__ src, int stride,
                                        float* __restrict__ dst, int tid) {
  #pragma unroll
  for (int it = 0; it < 2; it++) {
    int idx = tid + it * NTHREADS;
    int j = idx & 63, d0 = (idx >> 6) << 2;
    float4 v;
    v.x = src[(d0 + 0) * stride + j];
    v.y = src[(d0 + 1) * stride + j];
    v.z = src[(d0 + 2) * stride + j];
    v.w = src[(d0 + 3) * stride + j];
    *(float4*)(dst + j * NW + d0) = v;
  }
}

// 4-row GEMM: dst(4x64)[:, {lane, lane+32}] = act(4x64) @ w, packed partials.
__device__ __forceinline__ void gemm4t(const float* __restrict__ act,
                                       const float* __restrict__ wt,
                                       int lane, ull acc0[4], ull acc1[4]) {
  const float* w0 = wt + lane * NW;
  const float* w1 = wt + (lane + 32) * NW;
  #pragma unroll 2
  for (int d = 0; d < 64; d += 4) {
    ulonglong2 wp0 = *(const ulonglong2*)(w0 + d);
    ulonglong2 wp1 = *(const ulonglong2*)(w1 + d);
    #pragma unroll
    for (int s = 0; s < 4; s++) {
      ulonglong2 a = *(const ulonglong2*)(act + s * 64 + d);
      acc0[s] = ffma2(a.x, wp0.x, acc0[s]);
      acc1[s] = ffma2(a.x, wp1.x, acc1[s]);
      acc0[s] = ffma2(a.y, wp0.y, acc0[s]);
      acc1[s] = ffma2(a.y, wp1.y, acc1[s]);
    }
  }
}

// Fused QKV projection for 4 rows: one act pass, 24 packed accumulators.
__device__ __forceinline__ void qkv_gemm4(const float* __restrict__ act,
                                          const float* __restrict__ wq,
                                          const float* __restrict__ wk,
                                          const float* __restrict__ wv,
                                          const float* bq, const float* bk,
                                          const float* bv, int lane,
                                          float* dq, float* dk, float* dv) {
  ull A0[4], A1[4], B0[4], B1[4], C0[4], C1[4];
  {
    float q0 = bq[lane], q1 = bq[lane + 32];
    float k0 = bk[lane], k1 = bk[lane + 32];
    float v0 = bv[lane], v1 = bv[lane + 32];
    #pragma unroll
    for (int s = 0; s < 4; s++) {
      A0[s] = pack2(q0, 0.f); A1[s] = pack2(q1, 0.f);
      B0[s] = pack2(k0, 0.f); B1[s] = pack2(k1, 0.f);
      C0[s] = pack2(v0, 0.f); C1[s] = pack2(v1, 0.f);
    }
  }
  const float* q0p = wq + lane * NW; const float* q1p = wq + (lane + 32) * NW;
  const float* k0p = wk + lane * NW; const float* k1p = wk + (lane + 32) * NW;
  const float* v0p = wv + lane * NW; const float* v1p = wv + (lane + 32) * NW;
  #pragma unroll 1
  for (int d = 0; d < 64; d += 4) {
    ulonglong2 wq0 = *(const ulonglong2*)(q0p + d);
    ulonglong2 wq1 = *(const ulonglong2*)(q1p + d);
    ulonglong2 wk0 = *(const ulonglong2*)(k0p + d);
    ulonglong2 wk1 = *(const ulonglong2*)(k1p + d);
    ulonglong2 wv0 = *(const ulonglong2*)(v0p + d);
    ulonglong2 wv1 = *(const ulonglong2*)(v1p + d);
    #pragma unroll
    for (int s = 0; s < 4; s++) {
      ulonglong2 a = *(const ulonglong2*)(act + s * 64 + d);
      A0[s] = ffma2(a.x, wq0.x, A0[s]);
      A1[s] = ffma2(a.x, wq1.x, A1[s]);
      B0[s] = ffma2(a.x, wk0.x, B0[s]);
      B1[s] = ffma2(a.x, wk1.x, B1[s]);
      C0[s] = ffma2(a.x, wv0.x, C0[s]);
      C1[s] = ffma2(a.x, wv1.x, C1[s]);
      A0[s] = ffma2(a.y, wq0.y, A0[s]);
      A1[s] = ffma2(a.y, wq1.y, A1[s]);
      B0[s] = ffma2(a.y, wk0.y, B0[s]);
      B1[s] = ffma2(a.y, wk1.y, B1[s]);
      C0[s] = ffma2(a.y, wv0.y, C0[s]);
      C1[s] = ffma2(a.y, wv1.y, C1[s]);
    }
  }
  #pragma unroll
  for (int s = 0; s < 4; s++) {
    float2 x;
    x = unpack2(A0[s]); dq[s * 64 + lane] = x.x + x.y;
    x = unpack2(A1[s]); dq[s * 64 + lane + 32] = x.x + x.y;
    x = unpack2(B0[s]); dk[s * 64 + lane] = x.x + x.y;
    x = unpack2(B1[s]); dk[s * 64 + lane + 32] = x.x + x.y;
    x = unpack2(C0[s]); dv[s * 64 + lane] = x.x + x.y;
    x = unpack2(C1[s]); dv[s * 64 + lane + 32] = x.x + x.y;
  }
}

// Fused cK+cV for 4 rows.
__device__ __forceinline__ void kv_gemm4(const float* __restrict__ act,
                                         const float* __restrict__ wk,
                                         const float* __restrict__ wv,
                                         const float* bk, const float* bv,
                                         int lane, float* dk, float* dv) {
  ull B0[4], B1[4], C0[4], C1[4];
  {
    float k0 = bk[lane], k1 = bk[lane + 32];
    float v0 = bv[lane], v1 = bv[lane + 32];
    #pragma unroll
    for (int s = 0; s < 4; s++) {
      B0[s] = pack2(k0, 0.f); B1[s] = pack2(k1, 0.f);
      C0[s] = pack2(v0, 0.f); C1[s] = pack2(v1, 0.f);
    }
  }
  const float* k0p = wk + lane * NW; const float* k1p = wk + (lane + 32) * NW;
  const float* v0p = wv + lane * NW; const float* v1p = wv + (lane + 32) * NW;
  #pragma unroll 1
  for (int d = 0; d < 64; d += 4) {
    ulonglong2 wk0 = *(const ulonglong2*)(k0p + d);
    ulonglong2 wk1 = *(const ulonglong2*)(k1p + d);
    ulonglong2 wv0 = *(const ulonglong2*)(v0p + d);
    ulonglong2 wv1 = *(const ulonglong2*)(v1p + d);
    #pragma unroll
    for (int s = 0; s < 4; s++) {
      ulonglong2 a = *(const ulonglong2*)(act + s * 64 + d);
      B0[s] = ffma2(a.x, wk0.x, B0[s]);
      B1[s] = ffma2(a.x, wk1.x, B1[s]);
      C0[s] = ffma2(a.x, wv0.x, C0[s]);
      C1[s] = ffma2(a.x, wv1.x, C1[s]);
      B0[s] = ffma2(a.y, wk0.y, B0[s]);
      B1[s] = ffma2(a.y, wk1.y, B1[s]);
      C0[s] = ffma2(a.y, wv0.y, C0[s]);
      C1[s] = ffma2(a.y, wv1.y, C1[s]);
    }
  }
  #pragma unroll
  for (int s = 0; s < 4; s++) {
    float2 x;
    x = unpack2(B0[s]); dk[s * 64 + lane] = x.x + x.y;
    x = unpack2(B1[s]); dk[s * 64 + lane + 32] = x.x + x.y;
    x = unpack2(C0[s]); dv[s * 64 + lane] = x.x + x.y;
    x = unpack2(C1[s]); dv[s * 64 + lane + 32] = x.x + x.y;
  }
}

// 4-row projection with bias, optional relu.
__device__ __forceinline__ void proj4(const float* act, const float* wt,
                                      const float* bias, int lane,
                                      float* dst, int do_relu) {
  ull a0[4], a1[4];
  float b0 = bias[lane], b1 = bias[lane + 32];
  #pragma unroll
  for (int s = 0; s < 4; s++) { a0[s] = pack2(b0, 0.f); a1[s] = pack2(b1, 0.f); }
  gemm4t(act, wt, lane, a0, a1);
  #pragma unroll
  for (int s = 0; s < 4; s++) {
    float2 x = unpack2(a0[s]);
    float2 y = unpack2(a1[s]);
    float r0 = x.x + x.y, r1 = y.x + y.y;
    if (do_relu) { r0 = fmaxf(r0, 0.f); r1 = fmaxf(r1, 0.f); }
    dst[s * 64 + lane] = r0;
    dst[s * 64 + lane + 32] = r1;
  }
}

// LayerNorm over 4 rows (this lane holds cols lane, lane+32)
__device__ __forceinline__ void layernorm4(const float v[8], const float* g,
                                           const float* be, int lane, float* dst) {
  float gg0 = g[lane], gg1 = g[lane + 32];
  float bb0 = be[lane], bb1 = be[lane + 32];
  #pragma unroll
  for (int s = 0; s < 4; s++) {
    float sum = v[2 * s] + v[2 * s + 1];
    #pragma unroll
    for (int o = 16; o > 0; o >>= 1) sum += __shfl_xor_sync(0xffffffffu, sum, o);
    float mean = sum * 0.015625f;
    float d0 = v[2 * s] - mean, d1 = v[2 * s + 1] - mean;
    float vs = d0 * d0 + d1 * d1;
    #pragma unroll
    for (int o = 16; o > 0; o >>= 1) vs += __shfl_xor_sync(0xffffffffu, vs, o);
    float rstd = rsqrtf(vs * 0.015625f + 1e-5f);
    dst[s * 64 + lane] = d0 * rstd * gg0 + bb0;
    dst[s * 64 + lane + 32] = d1 * rstd * gg1 + bb1;
  }
}

__global__ void __launch_bounds__(NTHREADS, 1) rt_kernel(Params p) {
  extern __shared__ float sm[];
  const int tid = threadIdx.x;
  const int warp = tid >> 5, lane = tid & 31;
  const int ray = warp & 7;           // 8 rays, 2 warps each
  const int half = warp >> 3;         // 0: rows 0-3, 1: rows 4-7
  const int rb = half * 4;            // row base
  const int b = blockIdx.x * RAYS + ray;

  float* s_w0 = sm + OFF_W0;
  float* s_w1 = sm + OFF_W1;
  float* s_w2 = sm + OFF_W2;
  float* s_w3 = sm + OFF_W3;
  float* s_qkv = sm + OFF_QKV;

  float* my_out = sm + OFF_OUT + ray * 512;  // full 8x64; this warp owns rows rb..rb+3
  float* my_a = sm + OFF_A + ray * 512;
  float* my_q = s_qkv + ray * 1536;
  float* my_k = my_q + 512;
  float* my_v = my_q + 1024;
  float* my_p = sm + OFF_P + ray * 64;

  float* act4 = my_out + rb * 64;     // this warp's 4 activation rows
  float* q4 = my_q + rb * 64;
  float* k4 = my_k + rb * 64;
  float* v4 = my_v + rb * 64;
  float* a4 = my_a + rb * 64;

  // ---------------- stage 0: out = relu(latent @ W1 + b1) ----------------
  {
    ull a0[4], a1[4];
    float b0v = p.b1[lane], b1v = p.b1[lane + 32];
    #pragma unroll
    for (int s = 0; s < 4; s++) { a0[s] = pack2(b0v, 0.f); a1[s] = pack2(b1v, 0.f); }
    float* lat0 = s_qkv;         // ping-pong latent staging (4096 each)
    float* lat1 = s_qkv + 4096;
    // prestage chunk 0
    stage_t(p.W1, 64, s_w0, tid);
    for (int i = tid; i < 4096; i += NTHREADS) {
      int r = i >> 9, rem = i & 511, s = rem >> 6, d = rem & 63;
      lat0[i] = p.latent[(size_t)(blockIdx.x * RAYS + r) * 4096 + (size_t)s * 512 + d];
    }
    __syncthreads();
    for (int kc = 0; kc < 8; kc++) {
      float* wb = (kc & 1) ? s_w1 : s_w0;
      float* lb = (kc & 1) ? lat1 : lat0;
      if (kc < 7) {
        float* wn = (kc & 1) ? s_w0 : s_w1;
        float* ln = (kc & 1) ? lat0 : lat1;
        stage_t(p.W1 + (kc + 1) * 4096, 64, wn, tid);
        for (int i = tid; i < 4096; i += NTHREADS) {
          int r = i >> 9, rem = i & 511, s = rem >> 6, d = rem & 63;
          ln[i] = p.latent[(size_t)(blockIdx.x * RAYS + r) * 4096 +
                           (size_t)s * 512 + (kc + 1) * 64 + d];
        }
      }
      gemm4t(lb + ray * 512 + rb * 64, wb, lane, a0, a1);
      __syncthreads();
    }
    #pragma unroll
    for (int s = 0; s < 4; s++) {
      float2 x = unpack2(a0[s]);
      float2 y = unpack2(a1[s]);
      act4[s * 64 + lane] = fmaxf(x.x + x.y, 0.f);
      act4[s * 64 + lane + 32] = fmaxf(y.x + y.y, 0.f);
    }
  }
  __syncthreads();

  // ---------------- 4 transformer layers ----------------
  for (int l = 0; l < 4; l++) {
    // stage head-0 QKV weights
    stage_t(p.Wq + l * 16384, 256, s_w0, tid);
    stage_t(p.Wk + l * 16384, 256, s_w1, tid);
    stage_t(p.Wv + l * 16384, 256, s_w2, tid);
    __syncthreads();

    for (int h = 0; h < 4; h++) {
      qkv_gemm4(act4, s_w0, s_w1, s_w2,
                p.bq + l * 256 + h * 64, p.bk + l * 256 + h * 64,
                p.bv + l * 256 + h * 64, lane, q4, k4, v4);
      __syncthreads();   // (A) K,V visible across the warp pair; w bufs free

      // overlap: stage Wo(h) and next weights while doing attention
      stage_t(p.Wo + l * 16384 + h * 4096, 64, s_w3, tid);
      if (h < 3) {
        stage_t(p.Wq + l * 16384 + (h + 1) * 64, 256, s_w0, tid);
        stage_t(p.Wk + l * 16384 + (h + 1) * 64, 256, s_w1, tid);
        stage_t(p.Wv + l * 16384 + (h + 1) * 64, 256, s_w2, tid);
      } else {
        stage_t(p.fW1 + l * 4096, 64, s_w1, tid);
        stage_t(p.fW2 + l * 4096, 64, s_w2, tid);
      }

      // ---- attention: this warp handles its 4 q rows ----
      {
        int qrow = rb + (lane >> 3);
        int k = lane & 7;
        const float* qr = my_q + qrow * 64;
        const float* kr = my_k + k * 64;
        ull acc = pack2(0.f, 0.f);
        #pragma unroll
        for (int j = 0; j < 64; j += 4) {
          ulonglong2 qq = *(const ulonglong2*)(qr + j);
          ulonglong2 kk = *(const ulonglong2*)(kr + j);
          acc = ffma2(qq.x, kk.x, acc);
          acc = ffma2(qq.y, kk.y, acc);
        }
        float2 t = unpack2(acc);
        float sc = (t.x + t.y) * 0.125f;
        float m = sc;
        m = fmaxf(m, __shfl_xor_sync(0xffffffffu, m, 1));
        m = fmaxf(m, __shfl_xor_sync(0xffffffffu, m, 2));
        m = fmaxf(m, __shfl_xor_sync(0xffffffffu, m, 4));
        float e = __expf(sc - m);
        float se = e;
        se += __shfl_xor_sync(0xffffffffu, se, 1);
        se += __shfl_xor_sync(0xffffffffu, se, 2);
        se += __shfl_xor_sync(0xffffffffu, se, 4);
        float pr = __fdividef(e, se);
        my_p[qrow * 8 + k] = pr;
        p.o_attn[(size_t)b * 1024 + (size_t)l * 256 + h * 64 + half * 32 + lane] = pr;
        __syncwarp();
        // context = prob @ V for this warp's 4 rows
        float cx[8];
        #pragma unroll
        for (int i = 0; i < 8; i++) cx[i] = 0.f;
        #pragma unroll
        for (int kk2 = 0; kk2 < 8; kk2++) {
          float vx = my_v[kk2 * 64 + lane];
          float vy = my_v[kk2 * 64 + lane + 32];
          #pragma unroll
          for (int ql = 0; ql < 4; ql++) {
            float pk = my_p[(rb + ql) * 8 + kk2];
            cx[2 * ql] = fmaf(pk, vx, cx[2 * ql]);
            cx[2 * ql + 1] = fmaf(pk, vy, cx[2 * ql + 1]);
          }
        }
        __syncwarp();
        #pragma unroll
        for (int ql = 0; ql < 4; ql++) {
          q4[ql * 64 + lane] = cx[2 * ql];        // Q slot reused as context
          q4[ql * 64 + lane + 32] = cx[2 * ql + 1];
        }
        __syncwarp();
      }
      __syncthreads();   // (B) staged weights visible

      // ---- out-proj: accumulate into my_a (own rows) ----
      {
        ull a0[4], a1[4];
        if (h == 0) {
          float o0 = p.bo[l * 64 + lane], o1 = p.bo[l * 64 + lane + 32];
          #pragma unroll
          for (int s = 0; s < 4; s++) { a0[s] = pack2(o0, 0.f); a1[s] = pack2(o1, 0.f); }
        } else {
          #pragma unroll
          for (int s = 0; s < 4; s++) {
            a0[s] = pack2(a4[s * 64 + lane], 0.f);
            a1[s] = pack2(a4[s * 64 + lane + 32], 0.f);
          }
        }
        gemm4t(q4, s_w3, lane, a0, a1);
        #pragma unroll
        for (int s = 0; s < 4; s++) {
          float2 x = unpack2(a0[s]);
          float2 y = unpack2(a1[s]);
          a4[s * 64 + lane] = x.x + x.y;
          a4[s * 64 + lane + 32] = y.x + y.y;
        }
      }
      __syncthreads();   // (C) protect w3 + Q/K/V rewrite next head
    }  // heads

    // ---- LN1 (own rows): out = LN(a + out) ----
    {
      float v[8];
      #pragma unroll
      for (int s = 0; s < 4; s++) {
        v[2 * s] = a4[s * 64 + lane] + act4[s * 64 + lane];
        v[2 * s + 1] = a4[s * 64 + lane + 32] + act4[s * 64 + lane + 32];
      }
      layernorm4(v, p.g1 + l * 64, p.be1 + l * 64, lane, act4);
    }
    __syncwarp();
    // ---- FF1 (w1 staged during h==3) ----
    proj4(act4, s_w1, p.fb1 + l * 64, lane, q4, 1);
    __syncwarp();
    // ---- FF2 + LN2 ----
    {
      ull a0[4], a1[4];
      float f0 = p.fb2[l * 64 + lane], f1 = p.fb2[l * 64 + lane + 32];
      #pragma unroll
      for (int s = 0; s < 4; s++) { a0[s] = pack2(f0, 0.f); a1[s] = pack2(f1, 0.f); }
      gemm4t(q4, s_w2, lane, a0, a1);
      float v[8];
      #pragma unroll
      for (int s = 0; s < 4; s++) {
        float2 x = unpack2(a0[s]);
        float2 y = unpack2(a1[s]);
        v[2 * s] = x.x + x.y + act4[s * 64 + lane];
        v[2 * s + 1] = y.x + y.y + act4[s * 64 + lane + 32];
      }
      layernorm4(v, p.g2 + l * 64, p.be2 + l * 64, lane, act4);
    }
    __syncthreads();     // layer end: w1/w2 reads done before next staging
  }  // layers

  // ---------------- write out state (own rows) ----------------
  #pragma unroll
  for (int s = 0; s < 4; s++) {
    p.o_out[(size_t)b * 512 + (rb + s) * 64 + lane] = act4[s * 64 + lane];
    p.o_out[(size_t)b * 512 + (rb + s) * 64 + lane + 32] = act4[s * 64 + lane + 32];
  }

  // ---------------- sigma = max_s(out) @ Ws + bs (low warp) ----------------
  if (half == 0) {
    float m0 = my_out[lane], m1 = my_out[lane + 32];
    #pragma unroll
    for (int s = 1; s < 8; s++) {
      m0 = fmaxf(m0, my_out[s * 64 + lane]);
      m1 = fmaxf(m1, my_out[s * 64 + lane + 32]);
    }
    float part = m0 * p.Ws[lane] + m1 * p.Ws[lane + 32];
    #pragma unroll
    for (int o = 16; o > 0; o >>= 1) part += __shfl_xor_sync(0xffffffffu, part, o);
    if (lane == 0) p.o_sigma[b] = part + p.bs[0];
  }

  // ---------------- cross attention + color ----------------
  my_p[lane + half * 32] = p.query[(size_t)b * 64 + lane + half * 32];

  float ca0 = 0.f, ca1 = 0.f;
  for (int h = 0; h < 4; h++) {
    stage_t(p.cWq + h * 64, 256, s_w3, tid);
    stage_t(p.cWk + h * 64, 256, s_w0, tid);
    stage_t(p.cWv + h * 64, 256, s_w1, tid);
    stage_t(p.cWo + h * 4096, 64, s_w2, tid);
    __syncthreads();
    // fused cK + cV projection for own rows
    kv_gemm4(act4, s_w0, s_w1, p.cbk + h * 64, p.cbv + h * 64, lane, k4, v4);
    float cq0 = 0.f, cq1 = 0.f;
    if (half == 0) {
      // cq = query @ cWq_h + cbq_h (1 row)
      ull aq0 = pack2(p.cbq[h * 64 + lane], 0.f);
      ull aq1 = pack2(p.cbq[h * 64 + lane + 32], 0.f);
      const float* w0 = s_w3 + lane * NW;
      const float* w1 = s_w3 + (lane + 32) * NW;
      #pragma unroll
      for (int d = 0; d < 64; d += 4) {
        ulonglong2 a = *(const ulonglong2*)(my_p + d);
        ulonglong2 wp0 = *(const ulonglong2*)(w0 + d);
        ulonglong2 wp1 = *(const ulonglong2*)(w1 + d);
        aq0 = ffma2(a.x, wp0.x, aq0);
        aq1 = ffma2(a.x, wp1.x, aq1);
        aq0 = ffma2(a.y, wp0.y, aq0);
        aq1 = ffma2(a.y, wp1.y, aq1);
      }
      float2 t0 = unpack2(aq0), t1 = unpack2(aq1);
      cq0 = t0.x + t0.y;
      cq1 = t1.x + t1.y;
    }
    __syncthreads();   // K,V complete across warp pair
    if (half == 0) {
      float e[8];
      #pragma unroll
      for (int k = 0; k < 8; k++) {
        float pk = cq0 * my_k[k * 64 + lane] + cq1 * my_k[k * 64 + lane + 32];
        #pragma unroll
        for (int o = 16; o > 0; o >>= 1) pk += __shfl_xor_sync(0xffffffffu, pk, o);
        e[k] = pk * 0.125f;
      }
      float mm = e[0];
      #pragma unroll
      for (int k = 1; k < 8; k++) mm = fmaxf(mm, e[k]);
      float prb[8], sum = 0.f;
      #pragma unroll
      for (int k = 0; k < 8; k++) { prb[k] = __expf(e[k] - mm); sum += prb[k]; }
      float inv = __fdividef(1.f, sum);
      float cx0 = 0.f, cx1 = 0.f;
      #pragma unroll
      for (int k = 0; k < 8; k++) {
        float pk = prb[k] * inv;
        cx0 = fmaf(pk, my_v[k * 64 + lane], cx0);
        cx1 = fmaf(pk, my_v[k * 64 + lane + 32], cx1);
      }
      my_q[lane] = cx0;
      my_q[lane + 32] = cx1;
      __syncwarp();
      // ca += ctx @ cWo_h (+ cbo at h==0)
      ull ac0, ac1;
      if (h == 0) {
        ac0 = pack2(p.cbo[lane], ca0);
        ac1 = pack2(p.cbo[lane + 32], ca1);
      } else {
        ac0 = pack2(ca0, 0.f);
        ac1 = pack2(ca1, 0.f);
      }
      const float* w0 = s_w2 + lane * NW;
      const float* w1 = s_w2 + (lane + 32) * NW;
      #pragma unroll
      for (int d = 0; d < 64; d += 4) {
        ulonglong2 a = *(const ulonglong2*)(my_q + d);
        ulonglong2 wp0 = *(const ulonglong2*)(w0 + d);
        ulonglong2 wp1 = *(const ulonglong2*)(w1 + d);
        ac0 = ffma2(a.x, wp0.x, ac0);
        ac1 = ffma2(a.x, wp1.x, ac1);
        ac0 = ffma2(a.y, wp0.y, ac0);
        ac1 = ffma2(a.y, wp1.y, ac1);
      }
      float2 t0 = unpack2(ac0), t1 = unpack2(ac1);
      ca0 = t0.x + t0.y;
      ca1 = t1.x + t1.y;
    }
    __syncthreads();   // protect weight buffers before next head's staging
  }

  // color = relu(ca) @ Wc + bc (low warp)
  if (half == 0) {
    float r0 = fmaxf(ca0, 0.f), r1 = fmaxf(ca1, 0.f);
    #pragma unroll
    for (int t = 0; t < 3; t++) {
      float part = r0 * p.Wc[lane * 3 + t] + r1 * p.Wc[(lane + 32) * 3 + t];
      #pragma unroll
      for (int o = 16; o > 0; o >>= 1) part += __shfl_xor_sync(0xffffffffu, part, o);
      if (lane == 0) p.o_color[(size_t)b * 3 + t] = part + p.bc[t];
    }
  }
}

extern "C" void kernel_launch(void* const* d_in, const int* in_sizes, int n_in,
                              void* d_out, int out_size) {
  Params p;
  p.query = (const float*)d_in[0];
  p.latent = (const float*)d_in[1];
  p.W1 = (const float*)d_in[2];
  p.b1 = (const float*)d_in[3];
  p.Wq = (const float*)d_in[4];
  p.bq = (const float*)d_in[5];
  p.Wk = (const float*)d_in[6];
  p.bk = (const float*)d_in[7];
  p.Wv = (const float*)d_in[8];
  p.bv = (const float*)d_in[9];
  p.Wo = (const float*)d_in[10];
  p.bo = (const float*)d_in[11];
  p.fW1 = (const float*)d_in[12];
  p.fb1 = (const float*)d_in[13];
  p.fW2 = (const float*)d_in[14];
  p.fb2 = (const float*)d_in[15];
  p.g1 = (const float*)d_in[16];
  p.be1 = (const float*)d_in[17];
  p.g2 = (const float*)d_in[18];
  p.be2 = (const float*)d_in[19];
  p.cWq = (const float*)d_in[20];
  p.cbq = (const float*)d_in[21];
  p.cWk = (const float*)d_in[22];
  p.cbk = (const float*)d_in[23];
  p.cWv = (const float*)d_in[24];
  p.cbv = (const float*)d_in[25];
  p.cWo = (const float*)d_in[26];
  p.cbo = (const float*)d_in[27];
  p.Wc = (const float*)d_in[28];
  p.bc = (const float*)d_in[29];
  p.Ws = (const float*)d_in[30];
  p.bs = (const float*)d_in[31];

  float* o = (float*)d_out;
  p.o_color = o;                                    // [B,1,3]
  p.o_sigma = o + (size_t)B_TOTAL * 3;              // [B,1]
  p.o_out = o + (size_t)B_TOTAL * 4;                // [B,8,64]
  p.o_attn = o + (size_t)B_TOTAL * 4 + (size_t)B_TOTAL * 512;  // [B,4,4,8,8]

  cudaFuncSetAttribute(rt_kernel, cudaFuncAttributeMaxDynamicSharedMemorySize,
                       SMEM_BYTES);
  rt_kernel<<<NBLOCKS, NTHREADS, SMEM_BYTES>>>(p);
}

// round 8
// speedup vs baseline: 1.5548x; 1.5548x over previous
#include <cuda_runtime.h>

typedef unsigned long long ull;
typedef unsigned int uint;

#define NTHREADS 256
#define RAYS 8
#define NBLOCKS 4096
#define B_TOTAL 32768
#define S72 72                  // padded row stride (floats) for all 64-row tiles

// smem layout (floats)
#define OFF_ACT 0               // activations 64x72
#define OFF_W0  4608
#define OFF_W1  (4608*2)
#define OFF_W2  (4608*3)
#define OFF_W3  (4608*4)
#define OFF_Q   (4608*5)
#define OFF_K   (4608*6)
#define OFF_V   (4608*7)
#define OFF_CTX (4608*8)
#define OFF_AO  (4608*9)
#define OFF_P   (4608*10)       // probs 8x64
#define SMEM_FLOATS (4608*10 + 512)
#define SMEM_BYTES (SMEM_FLOATS * 4)

struct Params {
  const float *query, *latent, *W1, *b1;
  const float *Wq, *bq, *Wk, *bk, *Wv, *bv, *Wo, *bo;
  const float *fW1, *fb1, *fW2, *fb2, *g1, *be1, *g2, *be2;
  const float *cWq, *cbq, *cWk, *cbk, *cWv, *cbv, *cWo, *cbo;
  const float *Wc, *bc, *Ws, *bs;
  float *o_color, *o_sigma, *o_out, *o_attn;
};

// ---------------- small helpers ----------------
__device__ __forceinline__ float tf32c(float x) {
  uint u;
  asm("cvt.rna.tf32.f32 %0, %1;" : "=r"(u) : "f"(x));
  return __uint_as_float(u);
}
__device__ __forceinline__ ull ffma2(ull a, ull b, ull c) {
  ull d;
  asm("fma.rn.f32x2 %0, %1, %2, %3;" : "=l"(d) : "l"(a), "l"(b), "l"(c));
  return d;
}
__device__ __forceinline__ ull pack2(float lo, float hi) {
  ull d;
  asm("mov.b64 %0, {%1, %2};" : "=l"(d) : "f"(lo), "f"(hi));
  return d;
}
__device__ __forceinline__ float2 unpack2(ull v) {
  float lo, hi;
  asm("mov.b64 {%0, %1}, %2;" : "=f"(lo), "=f"(hi) : "l"(v));
  return make_float2(lo, hi);
}

// m16n8k8 tf32 mma, D=C in place
__device__ __forceinline__ void mma8(float c[4], uint a0, uint a1, uint a2, uint a3,
                                     uint b0, uint b1) {
  asm("mma.sync.aligned.m16n8k8.row.col.f32.tf32.tf32.f32 "
      "{%0,%1,%2,%3},{%4,%5,%6,%7},{%8,%9},{%0,%1,%2,%3};"
      : "+f"(c[0]), "+f"(c[1]), "+f"(c[2]), "+f"(c[3])
      : "r"(a0), "r"(a1), "r"(a2), "r"(a3), "r"(b0), "r"(b1));
}

// C[64x64] += A[64x64] @ W[64x64]; A f32 smem [64][72]; W tf32-bits smem [64][72].
// This warp: M-tile mt (rows mt*16..+15), N-half nh (cols nh*32..+31), 4 n-tiles.
__device__ __forceinline__ void gemm_acc(const float* __restrict__ A,
                                         const float* __restrict__ W,
                                         int lane, int mt, int nh, float c[4][4]) {
  const int grp = lane >> 2, kq = lane & 3;
  const float* ar = A + (mt * 16 + grp) * S72 + kq;
  const uint* Wu = (const uint*)W;
  #pragma unroll
  for (int kk = 0; kk < 8; kk++) {
    uint a0 = __float_as_uint(tf32c(ar[kk * 8]));
    uint a1 = __float_as_uint(tf32c(ar[8 * S72 + kk * 8]));
    uint a2 = __float_as_uint(tf32c(ar[kk * 8 + 4]));
    uint a3 = __float_as_uint(tf32c(ar[8 * S72 + kk * 8 + 4]));
    const uint* wb = Wu + (kk * 8 + kq) * S72 + nh * 32 + grp;
    #pragma unroll
    for (int t = 0; t < 4; t++)
      mma8(c[t], a0, a1, a2, a3, wb[t * 8], wb[4 * S72 + t * 8]);
  }
}

// store C frags to smem [64][72] with bias (global ptr), optional relu/residual
__device__ __forceinline__ void store_c(float* D, int lane, int mt, int nh,
                                        const float c[4][4], const float* bias,
                                        int do_relu, const float* resid) {
  const int grp = lane >> 2, kq = lane & 3;
  const int r = mt * 16 + grp;
  #pragma unroll
  for (int t = 0; t < 4; t++) {
    int col = nh * 32 + t * 8 + 2 * kq;
    float b0 = __ldg(bias + col), b1 = __ldg(bias + col + 1);
    float v0 = c[t][0] + b0, v1 = c[t][1] + b1;
    float v2 = c[t][2] + b0, v3 = c[t][3] + b1;
    if (resid) {
      v0 += resid[r * S72 + col];
      v1 += resid[r * S72 + col + 1];
      v2 += resid[(r + 8) * S72 + col];
      v3 += resid[(r + 8) * S72 + col + 1];
    }
    if (do_relu) {
      v0 = fmaxf(v0, 0.f); v1 = fmaxf(v1, 0.f);
      v2 = fmaxf(v2, 0.f); v3 = fmaxf(v3, 0.f);
    }
    *(float2*)(D + r * S72 + col) = make_float2(v0, v1);
    *(float2*)(D + (r + 8) * S72 + col) = make_float2(v2, v3);
  }
}

// stage 64x64 weight block into [64][72] smem; tocvt: convert to tf32 bits
__device__ __forceinline__ void stage_w(const float* __restrict__ src, int stride,
                                        float* __restrict__ dst, int tid, int tocvt) {
  #pragma unroll
  for (int it = 0; it < 4; it++) {
    int i = tid + it * NTHREADS;
    int d = i >> 4, j = (i & 15) * 4;
    float4 v = *(const float4*)(src + d * stride + j);
    if (tocvt) { v.x = tf32c(v.x); v.y = tf32c(v.y); v.z = tf32c(v.z); v.w = tf32c(v.w); }
    *(float4*)(dst + d * S72 + j) = v;
  }
}

// LayerNorm of 8 rows of (s1 [+ s2]) -> dst rows; lane owns cols lane, lane+32
__device__ __forceinline__ void ln_rows(const float* s1, const float* s2,
                                        const float* g, const float* be,
                                        int lane, float* dst) {
  float gg0 = __ldg(g + lane), gg1 = __ldg(g + lane + 32);
  float bb0 = __ldg(be + lane), bb1 = __ldg(be + lane + 32);
  #pragma unroll
  for (int s = 0; s < 8; s++) {
    float x0 = s1[s * S72 + lane];
    float x1 = s1[s * S72 + lane + 32];
    if (s2) { x0 += s2[s * S72 + lane]; x1 += s2[s * S72 + lane + 32]; }
    float sum = x0 + x1;
    #pragma unroll
    for (int o = 16; o > 0; o >>= 1) sum += __shfl_xor_sync(0xffffffffu, sum, o);
    float mean = sum * 0.015625f;
    float d0 = x0 - mean, d1 = x1 - mean;
    float vs = d0 * d0 + d1 * d1;
    #pragma unroll
    for (int o = 16; o > 0; o >>= 1) vs += __shfl_xor_sync(0xffffffffu, vs, o);
    float rstd = rsqrtf(vs * 0.015625f + 1e-5f);
    dst[s * S72 + lane] = d0 * rstd * gg0 + bb0;
    dst[s * S72 + lane + 32] = d1 * rstd * gg1 + bb1;
  }
}

#define STAGE_LAT(DST, KC)                                                     \
  do {                                                                         \
    _Pragma("unroll")                                                          \
    for (int it_ = 0; it_ < 4; it_++) {                                        \
      int i_ = tid + it_ * NTHREADS;                                           \
      int row_ = i_ >> 4, j_ = (i_ & 15) * 4;                                  \
      *(float4*)((DST) + row_ * S72 + j_) =                                    \
          *(const float4*)(p.latent + (size_t)(bbase + (row_ >> 3)) * 4096 +   \
                           (row_ & 7) * 512 + (KC) * 64 + j_);                 \
    }                                                                          \
  } while (0)

__global__ void __launch_bounds__(NTHREADS, 1) rt_kernel(Params p) {
  extern __shared__ float sm[];
  const int tid = threadIdx.x;
  const int warp = tid >> 5, lane = tid & 31;
  const int mt = warp & 3, nh = warp >> 2;   // mma roles
  const int ray = warp;                      // scalar roles
  const int bbase = blockIdx.x * RAYS;
  const int b = bbase + ray;

  float* s_act = sm + OFF_ACT;
  float* s_w0 = sm + OFF_W0;
  float* s_w1 = sm + OFF_W1;
  float* s_w2 = sm + OFF_W2;
  float* s_w3 = sm + OFF_W3;
  float* s_q = sm + OFF_Q;
  float* s_k = sm + OFF_K;
  float* s_v = sm + OFF_V;
  float* s_ctx = sm + OFF_CTX;
  float* s_ao = sm + OFF_AO;
  float* my_p = sm + OFF_P + ray * 64;

  // ---------------- stage 0: act = relu(latent @ W1 + b1), K=512 ----------------
  {
    float* lat0 = s_q;
    float* lat1 = s_k;
    stage_w(p.W1, 64, s_w0, tid, 1);
    STAGE_LAT(lat0, 0);
    __syncthreads();
    float c[4][4] = {};
    for (int kc = 0; kc < 8; kc++) {
      const float* lb = (kc & 1) ? lat1 : lat0;
      const float* wb = (kc & 1) ? s_w1 : s_w0;
      if (kc < 7) {
        stage_w(p.W1 + (kc + 1) * 4096, 64, (kc & 1) ? s_w0 : s_w1, tid, 1);
        STAGE_LAT((kc & 1) ? lat0 : lat1, kc + 1);
      }
      gemm_acc(lb, wb, lane, mt, nh, c);
      __syncthreads();
    }
    store_c(s_act, lane, mt, nh, c, p.b1, 1, nullptr);
  }
  __syncthreads();

  // ---------------- 4 transformer layers ----------------
  for (int l = 0; l < 4; l++) {
    stage_w(p.Wq + l * 16384, 256, s_w0, tid, 1);
    stage_w(p.Wk + l * 16384, 256, s_w1, tid, 1);
    stage_w(p.Wv + l * 16384, 256, s_w2, tid, 1);
    __syncthreads();

    float co[4][4] = {};   // out-proj accumulator across heads
    for (int h = 0; h < 4; h++) {
      // QKV gemms (tensor)
      {
        float c[4][4] = {};
        gemm_acc(s_act, s_w0, lane, mt, nh, c);
        store_c(s_q, lane, mt, nh, c, p.bq + l * 256 + h * 64, 0, nullptr);
      }
      {
        float c[4][4] = {};
        gemm_acc(s_act, s_w1, lane, mt, nh, c);
        store_c(s_k, lane, mt, nh, c, p.bk + l * 256 + h * 64, 0, nullptr);
      }
      {
        float c[4][4] = {};
        gemm_acc(s_act, s_w2, lane, mt, nh, c);
        store_c(s_v, lane, mt, nh, c, p.bv + l * 256 + h * 64, 0, nullptr);
      }
      __syncthreads();   // (A) QKV visible

      // stage next weights; LDG latency overlapped by attention below
      stage_w(p.Wo + l * 16384 + h * 4096, 64, s_w3, tid, 1);
      if (h < 3) {
        stage_w(p.Wq + l * 16384 + (h + 1) * 64, 256, s_w0, tid, 1);
        stage_w(p.Wk + l * 16384 + (h + 1) * 64, 256, s_w1, tid, 1);
        stage_w(p.Wv + l * 16384 + (h + 1) * 64, 256, s_w2, tid, 1);
      } else {
        stage_w(p.fW1 + l * 4096, 64, s_w0, tid, 1);
        stage_w(p.fW2 + l * 4096, 64, s_w1, tid, 1);
      }

      // ---- attention (scalar fp32, warp = ray) ----
      {
        const float* qb = s_q + ray * 8 * S72;
        const float* kb = s_k + ray * 8 * S72;
        const float* vb = s_v + ray * 8 * S72;
        float pr[2];
        #pragma unroll
        for (int u = 0; u < 2; u++) {
          int idx = lane + u * 32;
          int qi = idx >> 3, ki = idx & 7;
          const float* qr = qb + qi * S72;
          const float* kr = kb + ki * S72;
          ull acc = pack2(0.f, 0.f);
          #pragma unroll
          for (int j = 0; j < 64; j += 4) {
            ulonglong2 qq = *(const ulonglong2*)(qr + j);
            ulonglong2 kk2 = *(const ulonglong2*)(kr + j);
            acc = ffma2(qq.x, kk2.x, acc);
            acc = ffma2(qq.y, kk2.y, acc);
          }
          float2 t = unpack2(acc);
          float sc = (t.x + t.y) * 0.125f;
          float m = sc;
          m = fmaxf(m, __shfl_xor_sync(0xffffffffu, m, 1));
          m = fmaxf(m, __shfl_xor_sync(0xffffffffu, m, 2));
          m = fmaxf(m, __shfl_xor_sync(0xffffffffu, m, 4));
          float e = __expf(sc - m);
          float se = e;
          se += __shfl_xor_sync(0xffffffffu, se, 1);
          se += __shfl_xor_sync(0xffffffffu, se, 2);
          se += __shfl_xor_sync(0xffffffffu, se, 4);
          pr[u] = __fdividef(e, se);
        }
        my_p[lane] = pr[0];
        my_p[lane + 32] = pr[1];
        size_t ab = (size_t)b * 1024 + (size_t)l * 256 + h * 64;
        p.o_attn[ab + lane] = pr[0];
        p.o_attn[ab + lane + 32] = pr[1];
        __syncwarp();
        // ctx = P @ V (8 rows, lane cols lane/lane+32)
        float cx[16];
        #pragma unroll
        for (int i = 0; i < 16; i++) cx[i] = 0.f;
        #pragma unroll
        for (int ki = 0; ki < 8; ki++) {
          float vx = vb[ki * S72 + lane];
          float vy = vb[ki * S72 + lane + 32];
          #pragma unroll
          for (int qi = 0; qi < 8; qi++) {
            float pk = my_p[qi * 8 + ki];
            cx[2 * qi] = fmaf(pk, vx, cx[2 * qi]);
            cx[2 * qi + 1] = fmaf(pk, vy, cx[2 * qi + 1]);
          }
        }
        float* cr = s_ctx + ray * 8 * S72;
        #pragma unroll
        for (int qi = 0; qi < 8; qi++) {
          cr[qi * S72 + lane] = cx[2 * qi];
          cr[qi * S72 + lane + 32] = cx[2 * qi + 1];
        }
      }
      __syncthreads();   // (B) ctx + staged weights visible

      // out-proj: co += ctx @ Wo_h (tensor)
      gemm_acc(s_ctx, s_w3, lane, mt, nh, co);
      // no sync needed: next iter's stores hit q/k/v, readers of ctx/w3 are
      // pre-sync-A(h+1) on every warp
    }  // heads

    store_c(s_ao, lane, mt, nh, co, p.bo + l * 64, 0, nullptr);
    __syncthreads();
    // LN1: act = LN(a_out + act)
    ln_rows(s_ao + ray * 8 * S72, s_act + ray * 8 * S72,
            p.g1 + l * 64, p.be1 + l * 64, lane, s_act + ray * 8 * S72);
    __syncthreads();
    // FF1 (w0 = fW1 staged during h==3)
    {
      float c[4][4] = {};
      gemm_acc(s_act, s_w0, lane, mt, nh, c);
      store_c(s_q, lane, mt, nh, c, p.fb1 + l * 64, 1, nullptr);
    }
    __syncthreads();
    // FF2 + residual
    {
      float c[4][4] = {};
      gemm_acc(s_q, s_w1, lane, mt, nh, c);
      store_c(s_ao, lane, mt, nh, c, p.fb2 + l * 64, 0, s_act);
    }
    __syncthreads();
    // LN2: act = LN(a_out)
    ln_rows(s_ao + ray * 8 * S72, nullptr,
            p.g2 + l * 64, p.be2 + l * 64, lane, s_act + ray * 8 * S72);
    __syncthreads();
  }  // layers

  // ---------------- sigma & out ----------------
  {
    const float* ar = s_act + ray * 8 * S72;
    float m0 = ar[lane], m1 = ar[lane + 32];
    #pragma unroll
    for (int s = 1; s < 8; s++) {
      m0 = fmaxf(m0, ar[s * S72 + lane]);
      m1 = fmaxf(m1, ar[s * S72 + lane + 32]);
    }
    float part = m0 * __ldg(p.Ws + lane) + m1 * __ldg(p.Ws + lane + 32);
    #pragma unroll
    for (int o = 16; o > 0; o >>= 1) part += __shfl_xor_sync(0xffffffffu, part, o);
    if (lane == 0) p.o_sigma[b] = part + __ldg(p.bs);
    #pragma unroll
    for (int s = 0; s < 8; s++) {
      p.o_out[(size_t)b * 512 + s * 64 + lane] = ar[s * S72 + lane];
      p.o_out[(size_t)b * 512 + s * 64 + lane + 32] = ar[s * S72 + lane + 32];
    }
  }

  // ---------------- cross attention + color ----------------
  float* qr = s_ao + ray * S72;  // query row (warp-local)
  qr[lane] = p.query[(size_t)b * 64 + lane];
  qr[lane + 32] = p.query[(size_t)b * 64 + lane + 32];
  __syncwarp();

  float ca0 = 0.f, ca1 = 0.f;
  for (int h = 0; h < 4; h++) {
    __syncthreads();   // protect weight bufs from previous head's scalar readers
    stage_w(p.cWk + h * 64, 256, s_w0, tid, 1);
    stage_w(p.cWv + h * 64, 256, s_w1, tid, 1);
    stage_w(p.cWq + h * 64, 256, s_w3, tid, 0);   // f32 (scalar use)
    stage_w(p.cWo + h * 4096, 64, s_w2, tid, 0);  // f32 (scalar use)
    __syncthreads();
    // cK, cV gemms (tensor)
    {
      float c[4][4] = {};
      gemm_acc(s_act, s_w0, lane, mt, nh, c);
      store_c(s_k, lane, mt, nh, c, p.cbk + h * 64, 0, nullptr);
    }
    {
      float c[4][4] = {};
      gemm_acc(s_act, s_w1, lane, mt, nh, c);
      store_c(s_v, lane, mt, nh, c, p.cbv + h * 64, 0, nullptr);
    }
    __syncthreads();
    // per-ray scalar: cq, scores, softmax, ctx, ca accum
    float cq0 = __ldg(p.cbq + h * 64 + lane);
    float cq1 = __ldg(p.cbq + h * 64 + lane + 32);
    #pragma unroll 8
    for (int k = 0; k < 64; k++) {
      float a = qr[k];
      cq0 = fmaf(a, s_w3[k * S72 + lane], cq0);
      cq1 = fmaf(a, s_w3[k * S72 + lane + 32], cq1);
    }
    const float* kb = s_k + ray * 8 * S72;
    const float* vb = s_v + ray * 8 * S72;
    float e[8];
    #pragma unroll
    for (int k = 0; k < 8; k++) {
      float pk = cq0 * kb[k * S72 + lane] + cq1 * kb[k * S72 + lane + 32];
      #pragma unroll
      for (int o = 16; o > 0; o >>= 1) pk += __shfl_xor_sync(0xffffffffu, pk, o);
      e[k] = pk * 0.125f;
    }
    float mm = e[0];
    #pragma unroll
    for (int k = 1; k < 8; k++) mm = fmaxf(mm, e[k]);
    float prb[8], sum = 0.f;
    #pragma unroll
    for (int k = 0; k < 8; k++) { prb[k] = __expf(e[k] - mm); sum += prb[k]; }
    float inv = __fdividef(1.f, sum);
    float cx0 = 0.f, cx1 = 0.f;
    #pragma unroll
    for (int k = 0; k < 8; k++) {
      float pk = prb[k] * inv;
      cx0 = fmaf(pk, vb[k * S72 + lane], cx0);
      cx1 = fmaf(pk, vb[k * S72 + lane + 32], cx1);
    }
    float* cr = s_ctx + ray * S72;
    cr[lane] = cx0;
    cr[lane + 32] = cx1;
    __syncwarp();
    if (h == 0) { ca0 = __ldg(p.cbo + lane); ca1 = __ldg(p.cbo + lane + 32); }
    #pragma unroll 8
    for (int k = 0; k < 64; k++) {
      float a = cr[k];
      ca0 = fmaf(a, s_w2[k * S72 + lane], ca0);
      ca1 = fmaf(a, s_w2[k * S72 + lane + 32], ca1);
    }
  }

  // color = relu(ca) @ Wc + bc
  {
    float r0 = fmaxf(ca0, 0.f), r1 = fmaxf(ca1, 0.f);
    #pragma unroll
    for (int t = 0; t < 3; t++) {
      float part = r0 * __ldg(p.Wc + lane * 3 + t) + r1 * __ldg(p.Wc + (lane + 32) * 3 + t);
      #pragma unroll
      for (int o = 16; o > 0; o >>= 1) part += __shfl_xor_sync(0xffffffffu, part, o);
      if (lane == 0) p.o_color[(size_t)b * 3 + t] = part + __ldg(p.bc + t);
    }
  }
}

extern "C" void kernel_launch(void* const* d_in, const int* in_sizes, int n_in,
                              void* d_out, int out_size) {
  Params p;
  p.query = (const float*)d_in[0];
  p.latent = (const float*)d_in[1];
  p.W1 = (const float*)d_in[2];
  p.b1 = (const float*)d_in[3];
  p.Wq = (const float*)d_in[4];
  p.bq = (const float*)d_in[5];
  p.Wk = (const float*)d_in[6];
  p.bk = (const float*)d_in[7];
  p.Wv = (const float*)d_in[8];
  p.bv = (const float*)d_in[9];
  p.Wo = (const float*)d_in[10];
  p.bo = (const float*)d_in[11];
  p.fW1 = (const float*)d_in[12];
  p.fb1 = (const float*)d_in[13];
  p.fW2 = (const float*)d_in[14];
  p.fb2 = (const float*)d_in[15];
  p.g1 = (const float*)d_in[16];
  p.be1 = (const float*)d_in[17];
  p.g2 = (const float*)d_in[18];
  p.be2 = (const float*)d_in[19];
  p.cWq = (const float*)d_in[20];
  p.cbq = (const float*)d_in[21];
  p.cWk = (const float*)d_in[22];
  p.cbk = (const float*)d_in[23];
  p.cWv = (const float*)d_in[24];
  p.cbv = (const float*)d_in[25];
  p.cWo = (const float*)d_in[26];
  p.cbo = (const float*)d_in[27];
  p.Wc = (const float*)d_in[28];
  p.bc = (const float*)d_in[29];
  p.Ws = (const float*)d_in[30];
  p.bs = (const float*)d_in[31];

  float* o = (float*)d_out;
  p.o_color = o;                                    // [B,1,3]
  p.o_sigma = o + (size_t)B_TOTAL * 3;              // [B,1]
  p.o_out = o + (size_t)B_TOTAL * 4;                // [B,8,64]
  p.o_attn = o + (size_t)B_TOTAL * 4 + (size_t)B_TOTAL * 512;  // [B,4,4,8,8]

  cudaFuncSetAttribute(rt_kernel, cudaFuncAttributeMaxDynamicSharedMemorySize,
                       SMEM_BYTES);
  rt_kernel<<<NBLOCKS, NTHREADS, SMEM_BYTES>>>(p);
}